// round 16
// baseline (speedup 1.0000x reference)
#include <cuda_runtime.h>

// out = segment_sum(x, batch); batch sorted int32, N=1e6, C=128, G=10000.
// softmax over size-1 axis == 1.0 -> W/b dead inputs.
// R16: R14 (best) with the pre-stream block barrier removed: every thread
// spins on its segment's two offset entries directly (same two cache lines,
// coalesced; only non-trivial during wave 1), so warps start streaming the
// moment offsets publish - no smem handoff, no entry __syncthreads.

#define C 128
#define C4 (C / 4)
#define WARPS 4
#define TPB (WARPS * 32)
#define MAX_SEG 10000
#define IPT 4                  // int4 elements per producer thread

__device__ int g_start1[MAX_SEG + 1];   // start[g]+1 ; 0 means not ready

__device__ __forceinline__ void f4add(float4& a, const float4& v) {
    a.x += v.x; a.y += v.y; a.z += v.z; a.w += v.w;
}

__global__ __launch_bounds__(TPB) void fused_kernel(
    const float4* __restrict__ x4,
    const int4*  __restrict__ batch4,
    const int*   __restrict__ batch,
    float4* __restrict__ out4,
    int n, int n4, int nwork, int nseg)
{
    const int g    = blockIdx.x;             // segment id == block id
    const int warp = threadIdx.x >> 5;
    const int lane = threadIdx.x & 31;       // channels [4*lane, 4*lane+4)

    // -------- producer role (first nwork blocks, then fall through) --------
    if (g < nwork) {
        int base = (g * TPB + threadIdx.x) * IPT;
        #pragma unroll
        for (int k = 0; k < IPT; ++k) {
            int i = base + k;
            if (i < n4) {
                int4 v = __ldg(&batch4[i]);
                int prev = (i == 0) ? -1 : __ldg(&batch[4 * i - 1]);
                if (v.x != prev) for (int q = prev + 1; q <= v.x; ++q) g_start1[q] = 4 * i + 1;
                if (v.y != v.x)  for (int q = v.x + 1;  q <= v.y; ++q) g_start1[q] = 4 * i + 2;
                if (v.z != v.y)  for (int q = v.y + 1;  q <= v.z; ++q) g_start1[q] = 4 * i + 3;
                if (v.w != v.z)  for (int q = v.z + 1;  q <= v.w; ++q) g_start1[q] = 4 * i + 4;
                if (4 * i + 4 >= n)
                    for (int q = v.w + 1; q <= nseg; ++q) g_start1[q] = n + 1;
            }
        }
        __threadfence();                     // publish to L2 for all consumers
    }

    // -------- consumer role: all threads spin on the two entries --------
    int s, e;
    {
        volatile int* vs = g_start1;
        int a = 0, b = 0;
        for (;;) {                           // broadcast loads, warp-convergent
            if (a == 0) a = vs[g];
            if (b == 0) b = vs[g + 1];
            if (a != 0 && b != 0) break;
            __nanosleep(32);
        }
        s = a - 1;
        e = b - 1;
    }

    float4 a0 = make_float4(0.f, 0.f, 0.f, 0.f);
    float4 a1 = make_float4(0.f, 0.f, 0.f, 0.f);
    float4 a2 = make_float4(0.f, 0.f, 0.f, 0.f);
    float4 a3 = make_float4(0.f, 0.f, 0.f, 0.f);

    const float4* p = x4 + (size_t)s * C4 + lane;
    int len = e - s;
    int r = warp;

    for (; r + 3 * WARPS < len; r += 4 * WARPS) {
        float4 v0 = __ldcs(p + (size_t)(r            ) * C4);
        float4 v1 = __ldcs(p + (size_t)(r +     WARPS) * C4);
        float4 v2 = __ldcs(p + (size_t)(r + 2 * WARPS) * C4);
        float4 v3 = __ldcs(p + (size_t)(r + 3 * WARPS) * C4);
        f4add(a0, v0); f4add(a1, v1); f4add(a2, v2); f4add(a3, v3);
    }
    for (; r < len; r += WARPS)
        f4add(a0, __ldcs(p + (size_t)r * C4));

    f4add(a0, a1); f4add(a2, a3); f4add(a0, a2);

    __shared__ float4 sacc[WARPS][C4];
    sacc[warp][lane] = a0;
    __syncthreads();

    if (warp == 0) {
        float4 a = sacc[0][lane], b = sacc[1][lane],
               c = sacc[2][lane], d = sacc[3][lane];
        a.x += b.x + c.x + d.x;
        a.y += b.y + c.y + d.y;
        a.z += b.z + c.z + d.z;
        a.w += b.w + c.w + d.w;
        __stcs(&out4[(size_t)g * C4 + lane], a);   // evict-first store
    }
}

extern "C" void kernel_launch(void* const* d_in, const int* in_sizes, int n_in,
                              void* d_out, int out_size)
{
    const float4* x4    = (const float4*)d_in[0];
    const int*    batch = (const int*)d_in[1];
    // d_in[2] = W, d_in[3] = b : dead (softmax over size-1 axis)
    float4* out4 = (float4*)d_out;

    const int n     = in_sizes[0] / C;       // rows of x (1e6, divisible by 4)
    const int nseg  = out_size / C;          // segments (10000)
    const int n4    = n / 4;                 // int4 elements of batch
    const int nwork = (n4 + TPB * IPT - 1) / (TPB * IPT);  // 489 producer blocks

    fused_kernel<<<nseg, TPB>>>(x4, (const int4*)batch, batch, out4,
                                n, n4, nwork, nseg);
}

// round 17
// speedup vs baseline: 1.1199x; 1.1199x over previous
#include <cuda_runtime.h>

// out = segment_sum(x, batch); batch sorted int32, N=1e6, C=128, G=10000.
// softmax over size-1 axis == 1.0 -> W/b dead inputs.
// FINAL (== R14, best at 79.97us): single kernel, grid = nseg. Lowest 489
// blocks first scatter segment offsets (start+1 encoding into g_start1;
// 0 = not ready, valid from zero-init), then all blocks consume: tid 0 spins
// on its segment's two entries, block streams its contiguous row range with
// LDG.128 __ldcs + quad accumulators, smem-reduces across 4 warps, and
// writes its output row with an evict-first __stcs store.
// Rejected by measurement: per-block binary search (R5/R7), PDL (R8, neutral),
// global rendezvous (R9), persistent grid (R13), 2-seg blocks (R15),
// all-thread spin (R16). Kernel runs ~1% above the compulsory-traffic floor.

#define C 128
#define C4 (C / 4)
#define WARPS 4
#define TPB (WARPS * 32)
#define MAX_SEG 10000
#define IPT 4                  // int4 elements per producer thread

__device__ int g_start1[MAX_SEG + 1];   // start[g]+1 ; 0 means not ready

__device__ __forceinline__ void f4add(float4& a, const float4& v) {
    a.x += v.x; a.y += v.y; a.z += v.z; a.w += v.w;
}

__global__ __launch_bounds__(TPB) void fused_kernel(
    const float4* __restrict__ x4,
    const int4*  __restrict__ batch4,
    const int*   __restrict__ batch,
    float4* __restrict__ out4,
    int n, int n4, int nwork, int nseg)
{
    const int g    = blockIdx.x;             // segment id == block id
    const int warp = threadIdx.x >> 5;
    const int lane = threadIdx.x & 31;       // channels [4*lane, 4*lane+4)

    // -------- producer role (first nwork blocks, then fall through) --------
    if (g < nwork) {
        int base = (g * TPB + threadIdx.x) * IPT;
        #pragma unroll
        for (int k = 0; k < IPT; ++k) {
            int i = base + k;
            if (i < n4) {
                int4 v = __ldg(&batch4[i]);
                int prev = (i == 0) ? -1 : __ldg(&batch[4 * i - 1]);
                if (v.x != prev) for (int q = prev + 1; q <= v.x; ++q) g_start1[q] = 4 * i + 1;
                if (v.y != v.x)  for (int q = v.x + 1;  q <= v.y; ++q) g_start1[q] = 4 * i + 2;
                if (v.z != v.y)  for (int q = v.y + 1;  q <= v.z; ++q) g_start1[q] = 4 * i + 3;
                if (v.w != v.z)  for (int q = v.z + 1;  q <= v.w; ++q) g_start1[q] = 4 * i + 4;
                if (4 * i + 4 >= n)
                    for (int q = v.w + 1; q <= nseg; ++q) g_start1[q] = n + 1;
            }
        }
        __threadfence();                     // publish to L2 for all consumers
    }

    // -------- consumer role: one block per segment --------
    __shared__ int s_se[2];
    if (threadIdx.x == 0) {
        volatile int* vs = g_start1;
        int a = 0, b = 0;
        for (;;) {                           // spin on both entries together
            if (a == 0) a = vs[g];
            if (b == 0) b = vs[g + 1];
            if (a != 0 && b != 0) break;
            __nanosleep(32);
        }
        s_se[0] = a - 1;
        s_se[1] = b - 1;
    }
    __syncthreads();
    const int s = s_se[0];
    const int e = s_se[1];

    float4 a0 = make_float4(0.f, 0.f, 0.f, 0.f);
    float4 a1 = make_float4(0.f, 0.f, 0.f, 0.f);
    float4 a2 = make_float4(0.f, 0.f, 0.f, 0.f);
    float4 a3 = make_float4(0.f, 0.f, 0.f, 0.f);

    const float4* p = x4 + (size_t)s * C4 + lane;
    int len = e - s;
    int r = warp;

    for (; r + 3 * WARPS < len; r += 4 * WARPS) {
        float4 v0 = __ldcs(p + (size_t)(r            ) * C4);
        float4 v1 = __ldcs(p + (size_t)(r +     WARPS) * C4);
        float4 v2 = __ldcs(p + (size_t)(r + 2 * WARPS) * C4);
        float4 v3 = __ldcs(p + (size_t)(r + 3 * WARPS) * C4);
        f4add(a0, v0); f4add(a1, v1); f4add(a2, v2); f4add(a3, v3);
    }
    for (; r < len; r += WARPS)
        f4add(a0, __ldcs(p + (size_t)r * C4));

    f4add(a0, a1); f4add(a2, a3); f4add(a0, a2);

    __shared__ float4 sacc[WARPS][C4];
    sacc[warp][lane] = a0;
    __syncthreads();

    if (warp == 0) {
        float4 a = sacc[0][lane], b = sacc[1][lane],
               c = sacc[2][lane], d = sacc[3][lane];
        a.x += b.x + c.x + d.x;
        a.y += b.y + c.y + d.y;
        a.z += b.z + c.z + d.z;
        a.w += b.w + c.w + d.w;
        __stcs(&out4[(size_t)g * C4 + lane], a);   // evict-first store
    }
}

extern "C" void kernel_launch(void* const* d_in, const int* in_sizes, int n_in,
                              void* d_out, int out_size)
{
    const float4* x4    = (const float4*)d_in[0];
    const int*    batch = (const int*)d_in[1];
    // d_in[2] = W, d_in[3] = b : dead (softmax over size-1 axis)
    float4* out4 = (float4*)d_out;

    const int n     = in_sizes[0] / C;       // rows of x (1e6, divisible by 4)
    const int nseg  = out_size / C;          // segments (10000)
    const int n4    = n / 4;                 // int4 elements of batch
    const int nwork = (n4 + TPB * IPT - 1) / (TPB * IPT);  // 489 producer blocks

    fused_kernel<<<nseg, TPB>>>(x4, (const int4*)batch, batch, out4,
                                n, n4, nwork, nseg);
}